// round 2
// baseline (speedup 1.0000x reference)
#include <cuda_runtime.h>
#include <math.h>

#define N_ATOMSC 100000
#define M_NBR    12
#define ORIG     92
#define NBRF     41
#define AF       64
#define G1       128          // 2*AF
#define NM       (N_ATOMSC*M_NBR)   // 1,200,000
#define OUTD     128
#define NCRY     2000
#define APC      50
#define EPSL     1e-5f

// ---------------- device scratch (static: no runtime allocation) --------
__device__ float g_x[N_ATOMSC*AF];              // current atom features
__device__ float g_P[N_ATOMSC*G1];              // x @ W_self
__device__ float g_Q[N_ATOMSC*G1];              // x @ W_nbr
__device__ float g_gated[(size_t)NM*G1];        // pre-BN gated (614 MB)
__device__ float g_ns[N_ATOMSC*AF];             // nbr_sumed
__device__ float g_s1[G1], g_ss1[G1], g_a1[G1], g_b1[G1];   // BN1 stats + folded scale/shift
__device__ float g_s2[AF], g_ss2[AF], g_a2[AF], g_b2[AF];   // BN2

__device__ __forceinline__ float softplusf(float x){
    // matches jax.nn.softplus = logaddexp(x, 0)
    return fmaxf(x, 0.f) + log1pf(expf(-fabsf(x)));
}

// ---------------- embed: x = atom_fea @ W_embed + b ---------------------
__global__ void __launch_bounds__(256) kEmbed(const float* __restrict__ A,
                                              const float* __restrict__ W,
                                              const float* __restrict__ b){
    __shared__ float sW[ORIG*AF];       // 23.5 KB
    __shared__ float sb[AF];
    __shared__ float sIn[8][4*ORIG];    // per-warp 4-row staging
    int tid = threadIdx.x;
    for (int i = tid; i < ORIG*AF; i += 256) sW[i] = W[i];
    if (tid < AF) sb[tid] = b[tid];
    __syncthreads();
    int warp = tid >> 5, lane = tid & 31;
    int gw = blockIdx.x*8 + warp, nw = gridDim.x*8;
    float b0 = sb[lane*2], b1 = sb[lane*2+1];
    for (int grp = gw; grp < N_ATOMSC/4; grp += nw){
        int base = grp*4;
        for (int i = lane; i < 4*ORIG; i += 32)
            sIn[warp][i] = A[base*ORIG + i];     // 4 rows are contiguous
        __syncwarp();
        float acc[4][2];
        #pragma unroll
        for (int r = 0; r < 4; r++){ acc[r][0] = b0; acc[r][1] = b1; }
        #pragma unroll 4
        for (int k = 0; k < ORIG; k++){
            float2 w = *(const float2*)&sW[k*AF + lane*2];
            #pragma unroll
            for (int r = 0; r < 4; r++){
                float xv = sIn[warp][r*ORIG + k];
                acc[r][0] = fmaf(xv, w.x, acc[r][0]);
                acc[r][1] = fmaf(xv, w.y, acc[r][1]);
            }
        }
        #pragma unroll
        for (int r = 0; r < 4; r++)
            *(float2*)&g_x[(base+r)*AF + lane*2] = make_float2(acc[r][0], acc[r][1]);
        __syncwarp();
    }
}

// ---------------- P/Q GEMM: out = g_x @ W (64 -> 128) -------------------
__global__ void __launch_bounds__(256) kPQ(const float* __restrict__ W, int which){
    __shared__ float sW[AF*G1];         // 32 KB
    __shared__ float sIn[8][4*AF];      // 8 KB
    int tid = threadIdx.x;
    for (int i = tid; i < AF*G1; i += 256) sW[i] = W[i];
    __syncthreads();
    float* out = which ? g_Q : g_P;
    int warp = tid >> 5, lane = tid & 31;
    int gw = blockIdx.x*8 + warp, nw = gridDim.x*8;
    for (int grp = gw; grp < N_ATOMSC/4; grp += nw){
        int base = grp*4;
        for (int i = lane; i < 4*AF; i += 32)
            sIn[warp][i] = g_x[base*AF + i];
        __syncwarp();
        float4 acc[4];
        #pragma unroll
        for (int r = 0; r < 4; r++) acc[r] = make_float4(0.f,0.f,0.f,0.f);
        #pragma unroll 8
        for (int k = 0; k < AF; k++){
            float4 w = *(const float4*)&sW[k*G1 + lane*4];
            #pragma unroll
            for (int r = 0; r < 4; r++){
                float xv = sIn[warp][r*AF + k];
                acc[r].x = fmaf(xv, w.x, acc[r].x);
                acc[r].y = fmaf(xv, w.y, acc[r].y);
                acc[r].z = fmaf(xv, w.z, acc[r].z);
                acc[r].w = fmaf(xv, w.w, acc[r].w);
            }
        }
        #pragma unroll
        for (int r = 0; r < 4; r++)
            *(float4*)&out[(base+r)*G1 + lane*4] = acc[r];
        __syncwarp();
    }
}

// ---------------- edge kernel: gated = P[n]+Q[j]+E@W_edge+b, + BN1 stats
__global__ void __launch_bounds__(256) kEdge(const float* __restrict__ E,
                                             const int*   __restrict__ NI,
                                             const float* __restrict__ Wf,
                                             const float* __restrict__ bf){
    __shared__ float sW[NBRF*G1];       // 20.5 KB (edge block of Wf)
    __shared__ float sb[G1];
    __shared__ float sIn[8][4*NBRF];
    int tid = threadIdx.x;
    for (int i = tid; i < NBRF*G1; i += 256) sW[i] = Wf[128*G1 + i];
    if (tid < G1) sb[tid] = bf[tid];
    __syncthreads();
    int warp = tid >> 5, lane = tid & 31;
    int gw = blockIdx.x*8 + warp, nw = gridDim.x*8;
    float ss[4] = {0,0,0,0}, sq[4] = {0,0,0,0};
    float4 bb = *(const float4*)&sb[lane*4];
    for (int grp = gw; grp < NM/4; grp += nw){
        int base = grp*4;
        for (int i = lane; i < 4*NBRF; i += 32)
            sIn[warp][i] = E[base*NBRF + i];    // 4 edge rows contiguous
        __syncwarp();
        float4 acc[4];
        #pragma unroll
        for (int r = 0; r < 4; r++){
            int row = base + r;
            int n = row / M_NBR;
            int j = NI[row];
            float4 p = *(const float4*)&g_P[n*G1 + lane*4];
            float4 q = *(const float4*)&g_Q[j*G1 + lane*4];
            acc[r].x = bb.x + p.x + q.x;
            acc[r].y = bb.y + p.y + q.y;
            acc[r].z = bb.z + p.z + q.z;
            acc[r].w = bb.w + p.w + q.w;
        }
        #pragma unroll 8
        for (int k = 0; k < NBRF; k++){
            float4 w = *(const float4*)&sW[k*G1 + lane*4];
            #pragma unroll
            for (int r = 0; r < 4; r++){
                float e = sIn[warp][r*NBRF + k];
                acc[r].x = fmaf(e, w.x, acc[r].x);
                acc[r].y = fmaf(e, w.y, acc[r].y);
                acc[r].z = fmaf(e, w.z, acc[r].z);
                acc[r].w = fmaf(e, w.w, acc[r].w);
            }
        }
        #pragma unroll
        for (int r = 0; r < 4; r++){
            *(float4*)&g_gated[(size_t)(base+r)*G1 + lane*4] = acc[r];
            ss[0] += acc[r].x; sq[0] += acc[r].x*acc[r].x;
            ss[1] += acc[r].y; sq[1] += acc[r].y*acc[r].y;
            ss[2] += acc[r].z; sq[2] += acc[r].z*acc[r].z;
            ss[3] += acc[r].w; sq[3] += acc[r].w*acc[r].w;
        }
        __syncwarp();
    }
    #pragma unroll
    for (int c = 0; c < 4; c++){
        atomicAdd(&g_s1 [lane*4 + c], ss[c]);
        atomicAdd(&g_ss1[lane*4 + c], sq[c]);
    }
}

// ---------------- BN1 finalize: fold gamma/beta, reset accumulators -----
__global__ void kBN1(const float* __restrict__ gam, const float* __restrict__ bet){
    int f = threadIdx.x;                // 128 threads
    float inv = 1.f / (float)NM;
    float m = g_s1[f]*inv;
    float v = g_ss1[f]*inv - m*m;
    float a = gam[f] * rsqrtf(v + EPSL);
    g_a1[f] = a;
    g_b1[f] = bet[f] - m*a;
    g_s1[f] = 0.f; g_ss1[f] = 0.f;      // ready for next use (graph replay-safe)
}

// ---------------- reduce: sigmoid*softplus, sum over neighbors ----------
__global__ void __launch_bounds__(256) kReduce(){
    __shared__ float red[256];
    int tid = threadIdx.x;
    int f = tid & 63;
    float a1 = g_a1[f],    b1 = g_b1[f];
    float a2 = g_a1[64+f], b2 = g_b1[64+f];
    float ssum = 0.f, ssq = 0.f;
    int n0 = (blockIdx.x*256 + tid) >> 6;
    int ns = (gridDim.x*256) >> 6;
    for (int n = n0; n < N_ATOMSC; n += ns){
        float acc = 0.f;
        size_t base = (size_t)n * (M_NBR*G1) + f;
        #pragma unroll
        for (int m = 0; m < M_NBR; m++){
            float zf = fmaf(g_gated[base + m*G1     ], a1, b1);
            float zc = fmaf(g_gated[base + m*G1 + 64], a2, b2);
            float sig = 1.f / (1.f + expf(-zf));
            acc += sig * softplusf(zc);
        }
        g_ns[n*AF + f] = acc;
        ssum += acc; ssq += acc*acc;
    }
    red[tid] = ssum; __syncthreads();
    if (tid < 64) atomicAdd(&g_s2[f],  red[tid] + red[tid+64] + red[tid+128] + red[tid+192]);
    __syncthreads();
    red[tid] = ssq; __syncthreads();
    if (tid < 64) atomicAdd(&g_ss2[f], red[tid] + red[tid+64] + red[tid+128] + red[tid+192]);
}

// ---------------- BN2 finalize ------------------------------------------
__global__ void kBN2(const float* __restrict__ gam, const float* __restrict__ bet){
    int f = threadIdx.x;                // 64 threads
    float inv = 1.f / (float)N_ATOMSC;
    float m = g_s2[f]*inv;
    float v = g_ss2[f]*inv - m*m;
    float a = gam[f] * rsqrtf(v + EPSL);
    g_a2[f] = a;
    g_b2[f] = bet[f] - m*a;
    g_s2[f] = 0.f; g_ss2[f] = 0.f;
}

// ---------------- residual update: x = softplus(x + BN2(ns)) ------------
__global__ void __launch_bounds__(256) kUpdate(){
    int i = blockIdx.x*256 + threadIdx.x;   // exact grid
    int f = i & 63;
    float z = g_x[i] + fmaf(g_ns[i], g_a2[f], g_b2[f]);
    g_x[i] = softplusf(z);
}

// ---------------- pool + FC + ReLU --------------------------------------
__global__ void __launch_bounds__(128) kPool(const int* __restrict__ cidx,
                                             const float* __restrict__ Wp,
                                             const float* __restrict__ bp,
                                             float* __restrict__ out){
    __shared__ float sm[AF];
    int c = blockIdx.x, tid = threadIdx.x;
    if (tid < AF){
        float s = 0.f;
        #pragma unroll 5
        for (int a = 0; a < APC; a++){
            int idx = cidx[c*APC + a];
            s += g_x[idx*AF + tid];
        }
        sm[tid] = s * (1.f/(float)APC);
    }
    __syncthreads();
    float acc = bp[tid];
    #pragma unroll 8
    for (int k = 0; k < AF; k++)
        acc = fmaf(sm[k], Wp[k*OUTD + tid], acc);
    out[c*OUTD + tid] = fmaxf(acc, 0.f);
}

// ---------------- launcher ----------------------------------------------
extern "C" void kernel_launch(void* const* d_in, const int* in_sizes, int n_in,
                              void* d_out, int out_size){
    const float* atom_fea = (const float*)d_in[0];
    const float* nbr_fea  = (const float*)d_in[1];
    const int*   nbr_idx  = (const int*)  d_in[2];
    const int*   cidx     = (const int*)  d_in[3];
    const float* W_embed  = (const float*)d_in[4];
    const float* b_embed  = (const float*)d_in[5];
    const float* W_full   = (const float*)d_in[6];
    const float* b_full   = (const float*)d_in[7];
    const float* g1       = (const float*)d_in[8];
    const float* be1      = (const float*)d_in[9];
    const float* g2       = (const float*)d_in[10];
    const float* be2      = (const float*)d_in[11];
    const float* Wp       = (const float*)d_in[12];
    const float* bp       = (const float*)d_in[13];
    float* out = (float*)d_out;

    kEmbed<<<512, 256>>>(atom_fea, W_embed, b_embed);
    for (int l = 0; l < 3; l++){
        const float* Wf = W_full + (size_t)l * 169 * G1;
        kPQ  <<<1024, 256>>>(Wf,           0);   // P = x @ W_self
        kPQ  <<<1024, 256>>>(Wf + 64*G1,   1);   // Q = x @ W_nbr
        kEdge<<<2048, 256>>>(nbr_fea, nbr_idx, Wf, b_full + l*G1);
        kBN1 <<<1, 128>>>(g1 + l*G1, be1 + l*G1);
        kReduce<<<1024, 256>>>();
        kBN2 <<<1, 64>>>(g2 + l*AF, be2 + l*AF);
        kUpdate<<<(N_ATOMSC*AF)/256, 256>>>();
    }
    kPool<<<NCRY, 128>>>(cidx, Wp, bp, out);
}

// round 4
// speedup vs baseline: 2.1090x; 2.1090x over previous
#include <cuda_runtime.h>
#include <math.h>
#include <stdint.h>

#define N_ATOMSC 100000
#define M_NBR    12
#define ORIG     92
#define NBRF     41
#define AF       64
#define G1       128
#define NM       (N_ATOMSC*M_NBR)
#define OUTD     128
#define NCRY     2000
#define APC      50
#define EPSL     1e-5f

#define NGROUPS  (N_ATOMSC*2)      // 200000 half-atoms (6 edge rows each)

// ---------------- device scratch ----------------------------------------
__device__ float g_x[N_ATOMSC*AF];
__device__ float g_P[N_ATOMSC*G1];
__device__ float g_Q[N_ATOMSC*G1];
__device__ float g_gated[(size_t)NM*G1];
__device__ float g_ns[N_ATOMSC*AF];
__device__ float g_s1[G1], g_ss1[G1], g_a1[G1], g_b1[G1];
__device__ float g_s2[AF], g_ss2[AF], g_a2[AF], g_b2[AF];

__device__ __forceinline__ float softplus_fast(float x){
    return fmaxf(x, 0.f) + __logf(1.f + __expf(-fabsf(x)));
}

// ---------------- embed: x = atom_fea @ W_embed + b ---------------------
__global__ void __launch_bounds__(256) kEmbed(const float* __restrict__ A,
                                              const float* __restrict__ W,
                                              const float* __restrict__ b){
    __shared__ float sW[ORIG*AF];
    __shared__ float sb_[AF];
    __shared__ float sIn[8][4*ORIG];
    int tid = threadIdx.x;
    for (int i = tid; i < ORIG*AF; i += 256) sW[i] = W[i];
    if (tid < AF) sb_[tid] = b[tid];
    __syncthreads();
    int warp = tid >> 5, lane = tid & 31;
    int gw = blockIdx.x*8 + warp, nw = gridDim.x*8;
    float b0 = sb_[lane*2], b1 = sb_[lane*2+1];
    for (int grp = gw; grp < N_ATOMSC/4; grp += nw){
        int base = grp*4;
        for (int i = lane; i < 4*ORIG; i += 32)
            sIn[warp][i] = A[base*ORIG + i];
        __syncwarp();
        float acc[4][2];
        #pragma unroll
        for (int r = 0; r < 4; r++){ acc[r][0] = b0; acc[r][1] = b1; }
        #pragma unroll 4
        for (int k = 0; k < ORIG; k++){
            float2 w = *(const float2*)&sW[k*AF + lane*2];
            #pragma unroll
            for (int r = 0; r < 4; r++){
                float xv = sIn[warp][r*ORIG + k];
                acc[r][0] = fmaf(xv, w.x, acc[r][0]);
                acc[r][1] = fmaf(xv, w.y, acc[r][1]);
            }
        }
        #pragma unroll
        for (int r = 0; r < 4; r++)
            *(float2*)&g_x[(base+r)*AF + lane*2] = make_float2(acc[r][0], acc[r][1]);
        __syncwarp();
    }
}

// ---------------- fused P/Q GEMM: P = x@W_self, Q = x@W_nbr -------------
// dynamic smem: sW[64][256] (P cols 0..127, Q cols 128..255)
__global__ void __launch_bounds__(256) kPQ2(const float* __restrict__ Wf){
    extern __shared__ float sW[];          // 65536 B
    __shared__ float sIn[8][4*AF];
    int tid = threadIdx.x;
    for (int i = tid; i < AF*256; i += 256){
        int k = i >> 8, c = i & 255;
        sW[i] = (c < G1) ? Wf[k*G1 + c] : Wf[(AF + k)*G1 + (c - G1)];
    }
    __syncthreads();
    int warp = tid >> 5, lane = tid & 31;
    int gw = blockIdx.x*8 + warp, nw = gridDim.x*8;
    const float4* sW4 = (const float4*)sW;
    for (int grp = gw; grp < N_ATOMSC/4; grp += nw){
        int base = grp*4;
        for (int i = lane; i < 4*AF; i += 32)
            sIn[warp][i] = g_x[base*AF + i];
        __syncwarp();
        float4 aP[4], aQ[4];
        #pragma unroll
        for (int r = 0; r < 4; r++){
            aP[r] = make_float4(0.f,0.f,0.f,0.f);
            aQ[r] = make_float4(0.f,0.f,0.f,0.f);
        }
        #pragma unroll 8
        for (int k = 0; k < AF; k++){
            float4 wp = sW4[k*64 + lane];
            float4 wq = sW4[k*64 + 32 + lane];
            #pragma unroll
            for (int r = 0; r < 4; r++){
                float xv = sIn[warp][r*AF + k];
                aP[r].x = fmaf(xv, wp.x, aP[r].x);
                aP[r].y = fmaf(xv, wp.y, aP[r].y);
                aP[r].z = fmaf(xv, wp.z, aP[r].z);
                aP[r].w = fmaf(xv, wp.w, aP[r].w);
                aQ[r].x = fmaf(xv, wq.x, aQ[r].x);
                aQ[r].y = fmaf(xv, wq.y, aQ[r].y);
                aQ[r].z = fmaf(xv, wq.z, aQ[r].z);
                aQ[r].w = fmaf(xv, wq.w, aQ[r].w);
            }
        }
        #pragma unroll
        for (int r = 0; r < 4; r++){
            *(float4*)&g_P[(base+r)*G1 + lane*4] = aP[r];
            *(float4*)&g_Q[(base+r)*G1 + lane*4] = aQ[r];
        }
        __syncwarp();
    }
}

// ---------------- edge kernel: gated = P[n]+Q[j]+E@W_edge+b, BN1 stats --
// warp = 6 edge rows (half an atom) x 128 cols; lane owns cols lane*4..+3
__global__ void __launch_bounds__(256, 4) kEdge(const float* __restrict__ E,
                                                const int*   __restrict__ NI,
                                                const float* __restrict__ Wf,
                                                const float* __restrict__ bf){
    __shared__ float sW[NBRF*G1];       // 20992 B
    __shared__ float sb[G1];
    __shared__ float sS[G1], sQ[G1];
    __shared__ float sIn[8][248];
    int tid = threadIdx.x;
    int wid = tid >> 5, lane = tid & 31;
    const float* WfE = Wf + 128*G1;
    for (int i = tid; i < NBRF*G1; i += 256) sW[i] = WfE[i];
    if (tid < G1){ sb[tid] = bf[tid]; sS[tid] = 0.f; sQ[tid] = 0.f; }
    __syncthreads();

    const float4* sW4 = (const float4*)sW;
    float4 bb = *(const float4*)&sb[lane*4];
    float cs0=0,cs1=0,cs2=0,cs3=0, cq0=0,cq1=0,cq2=0,cq3=0;

    int gw = blockIdx.x*8 + wid, nw = gridDim.x*8;
    for (int g = gw; g < NGROUPS; g += nw){
        int n  = g >> 1;
        int rb = g*6;
        // stage 6 edge rows of E (246 floats, coalesced)
        const float* Ew = E + (size_t)rb * NBRF;
        #pragma unroll
        for (int i = lane; i < 6*NBRF; i += 32) sIn[wid][i] = Ew[i];
        // P once per group (rows share n), Q per row
        float4 p = *(const float4*)&g_P[(size_t)n*G1 + lane*4];
        float4 acc[6];
        #pragma unroll
        for (int r = 0; r < 6; r++){
            int j = NI[rb + r];
            float4 q = *(const float4*)&g_Q[(size_t)j*G1 + lane*4];
            acc[r].x = bb.x + p.x + q.x;
            acc[r].y = bb.y + p.y + q.y;
            acc[r].z = bb.z + p.z + q.z;
            acc[r].w = bb.w + p.w + q.w;
        }
        __syncwarp();
        #pragma unroll
        for (int k = 0; k < NBRF; k++){
            float4 w = sW4[k*32 + lane];
            #pragma unroll
            for (int r = 0; r < 6; r++){
                float e = sIn[wid][r*NBRF + k];
                acc[r].x = fmaf(e, w.x, acc[r].x);
                acc[r].y = fmaf(e, w.y, acc[r].y);
                acc[r].z = fmaf(e, w.z, acc[r].z);
                acc[r].w = fmaf(e, w.w, acc[r].w);
            }
        }
        #pragma unroll
        for (int r = 0; r < 6; r++){
            *(float4*)&g_gated[(size_t)(rb+r)*G1 + lane*4] = acc[r];
            cs0 += acc[r].x; cq0 = fmaf(acc[r].x, acc[r].x, cq0);
            cs1 += acc[r].y; cq1 = fmaf(acc[r].y, acc[r].y, cq1);
            cs2 += acc[r].z; cq2 = fmaf(acc[r].z, acc[r].z, cq2);
            cs3 += acc[r].w; cq3 = fmaf(acc[r].w, acc[r].w, cq3);
        }
        __syncwarp();
    }
    // block-level stat reduction, then 2 global atomics per column
    atomicAdd(&sS[lane*4+0], cs0); atomicAdd(&sQ[lane*4+0], cq0);
    atomicAdd(&sS[lane*4+1], cs1); atomicAdd(&sQ[lane*4+1], cq1);
    atomicAdd(&sS[lane*4+2], cs2); atomicAdd(&sQ[lane*4+2], cq2);
    atomicAdd(&sS[lane*4+3], cs3); atomicAdd(&sQ[lane*4+3], cq3);
    __syncthreads();
    if (tid < G1){
        atomicAdd(&g_s1[tid],  sS[tid]);
        atomicAdd(&g_ss1[tid], sQ[tid]);
    }
}

// ---------------- BN1 finalize -------------------------------------------
__global__ void kBN1(const float* __restrict__ gam, const float* __restrict__ bet){
    int f = threadIdx.x;
    float inv = 1.f / (float)NM;
    float m = g_s1[f]*inv;
    float v = g_ss1[f]*inv - m*m;
    float a = gam[f] * rsqrtf(v + EPSL);
    g_a1[f] = a;
    g_b1[f] = bet[f] - m*a;
    g_s1[f] = 0.f; g_ss1[f] = 0.f;
}

// ---------------- reduce: sigmoid*softplus, neighbor sum, BN2 stats -----
// warp = atoms; lane owns features f2 = lane*2, lane*2+1 (float2 loads)
__global__ void __launch_bounds__(256) kReduce(){
    __shared__ float rs[AF], rq[AF];
    int tid = threadIdx.x;
    int wid = tid >> 5, lane = tid & 31;
    if (tid < AF){ rs[tid] = 0.f; rq[tid] = 0.f; }
    __syncthreads();
    int f2 = lane*2;
    float A1x = g_a1[f2],    A1y = g_a1[f2+1];
    float B1x = g_b1[f2],    B1y = g_b1[f2+1];
    float A2x = g_a1[64+f2], A2y = g_a1[64+f2+1];
    float B2x = g_b1[64+f2], B2y = g_b1[64+f2+1];
    float s0=0,s1=0,q0=0,q1=0;
    int gw = blockIdx.x*8 + wid, nw = gridDim.x*8;
    for (int n = gw; n < N_ATOMSC; n += nw){
        const float* base = g_gated + (size_t)n*(M_NBR*G1) + f2;
        float a0 = 0.f, a1 = 0.f;
        #pragma unroll
        for (int m = 0; m < M_NBR; m++){
            float2 zf = *(const float2*)(base + m*G1);
            float2 zc = *(const float2*)(base + m*G1 + 64);
            float xf0 = fmaf(zf.x, A1x, B1x);
            float xf1 = fmaf(zf.y, A1y, B1y);
            float xc0 = fmaf(zc.x, A2x, B2x);
            float xc1 = fmaf(zc.y, A2y, B2y);
            float sg0 = __fdividef(1.f, 1.f + __expf(-xf0));
            float sg1 = __fdividef(1.f, 1.f + __expf(-xf1));
            a0 = fmaf(sg0, softplus_fast(xc0), a0);
            a1 = fmaf(sg1, softplus_fast(xc1), a1);
        }
        *(float2*)&g_ns[(size_t)n*AF + f2] = make_float2(a0, a1);
        s0 += a0; q0 = fmaf(a0, a0, q0);
        s1 += a1; q1 = fmaf(a1, a1, q1);
    }
    atomicAdd(&rs[f2],   s0); atomicAdd(&rq[f2],   q0);
    atomicAdd(&rs[f2+1], s1); atomicAdd(&rq[f2+1], q1);
    __syncthreads();
    if (tid < AF){
        atomicAdd(&g_s2[tid],  rs[tid]);
        atomicAdd(&g_ss2[tid], rq[tid]);
    }
}

// ---------------- BN2 finalize ------------------------------------------
__global__ void kBN2(const float* __restrict__ gam, const float* __restrict__ bet){
    int f = threadIdx.x;
    float inv = 1.f / (float)N_ATOMSC;
    float m = g_s2[f]*inv;
    float v = g_ss2[f]*inv - m*m;
    float a = gam[f] * rsqrtf(v + EPSL);
    g_a2[f] = a;
    g_b2[f] = bet[f] - m*a;
    g_s2[f] = 0.f; g_ss2[f] = 0.f;
}

// ---------------- residual update: x = softplus(x + BN2(ns)) ------------
__global__ void __launch_bounds__(256) kUpdate(){
    int i4 = blockIdx.x*256 + threadIdx.x;      // float4 index
    int f = (i4 & 15) * 4;
    float4 xv = *(const float4*)&g_x[i4*4];
    float4 nv = *(const float4*)&g_ns[i4*4];
    float4 a2 = *(const float4*)&g_a2[f];
    float4 b2 = *(const float4*)&g_b2[f];
    float4 o;
    o.x = softplus_fast(xv.x + fmaf(nv.x, a2.x, b2.x));
    o.y = softplus_fast(xv.y + fmaf(nv.y, a2.y, b2.y));
    o.z = softplus_fast(xv.z + fmaf(nv.z, a2.z, b2.z));
    o.w = softplus_fast(xv.w + fmaf(nv.w, a2.w, b2.w));
    *(float4*)&g_x[i4*4] = o;
}

// ---------------- pool + FC + ReLU ---------------------------------------
__global__ void __launch_bounds__(128) kPool(const int* __restrict__ cidx,
                                             const float* __restrict__ Wp,
                                             const float* __restrict__ bp,
                                             float* __restrict__ out){
    __shared__ float sm[AF];
    int c = blockIdx.x, tid = threadIdx.x;
    if (tid < AF){
        float s = 0.f;
        #pragma unroll 5
        for (int a = 0; a < APC; a++){
            int idx = cidx[c*APC + a];
            s += g_x[idx*AF + tid];
        }
        sm[tid] = s * (1.f/(float)APC);
    }
    __syncthreads();
    float acc = bp[tid];
    #pragma unroll 8
    for (int k = 0; k < AF; k++)
        acc = fmaf(sm[k], Wp[k*OUTD + tid], acc);
    out[c*OUTD + tid] = fmaxf(acc, 0.f);
}

// ---------------- launcher ------------------------------------------------
extern "C" void kernel_launch(void* const* d_in, const int* in_sizes, int n_in,
                              void* d_out, int out_size){
    const float* atom_fea = (const float*)d_in[0];
    const float* nbr_fea  = (const float*)d_in[1];
    const int*   nbr_idx  = (const int*)  d_in[2];
    const int*   cidx     = (const int*)  d_in[3];
    const float* W_embed  = (const float*)d_in[4];
    const float* b_embed  = (const float*)d_in[5];
    const float* W_full   = (const float*)d_in[6];
    const float* b_full   = (const float*)d_in[7];
    const float* g1       = (const float*)d_in[8];
    const float* be1      = (const float*)d_in[9];
    const float* g2       = (const float*)d_in[10];
    const float* be2      = (const float*)d_in[11];
    const float* Wp       = (const float*)d_in[12];
    const float* bp       = (const float*)d_in[13];
    float* out = (float*)d_out;

    static int attr_set = 0;
    if (!attr_set){
        cudaFuncSetAttribute(kPQ2, cudaFuncAttributeMaxDynamicSharedMemorySize, AF*256*4);
        attr_set = 1;
    }

    kEmbed<<<512, 256>>>(atom_fea, W_embed, b_embed);
    for (int l = 0; l < 3; l++){
        const float* Wf = W_full + (size_t)l * 169 * G1;
        kPQ2 <<<740, 256, AF*256*4>>>(Wf);
        kEdge<<<592, 256>>>(nbr_fea, nbr_idx, Wf, b_full + l*G1);
        kBN1 <<<1, 128>>>(g1 + l*G1, be1 + l*G1);
        kReduce<<<1024, 256>>>();
        kBN2 <<<1, 64>>>(g2 + l*AF, be2 + l*AF);
        kUpdate<<<(N_ATOMSC*AF/4)/256, 256>>>();
    }
    kPool<<<NCRY, 128>>>(cidx, Wp, bp, out);
}

// round 5
// speedup vs baseline: 2.1246x; 1.0074x over previous
#include <cuda_runtime.h>
#include <cuda_fp16.h>
#include <math.h>
#include <stdint.h>

#define N_ATOMSC 100000
#define M_NBR    12
#define ORIG     92
#define NBRF     41
#define NBRP     42            // padded (even) row width for float2 chunks
#define AF       64
#define G1       128
#define NM       (N_ATOMSC*M_NBR)
#define OUTD     128
#define NCRY     2000
#define APC      50
#define EPSL     1e-5f

#define NGROUPS  (N_ATOMSC*2)  // 200000 half-atoms (6 edge rows each)

typedef unsigned long long u64;

// ---------------- device scratch ----------------------------------------
__device__ float   g_x[N_ATOMSC*AF];
__device__ float   g_P[N_ATOMSC*G1];
__device__ float   g_Q[N_ATOMSC*G1];
__device__ __half2 g_gated[(size_t)NM*(G1/2)];     // fp16 gated (307 MB)
__device__ float   g_ns[N_ATOMSC*AF];
__device__ float   g_s1[G1], g_ss1[G1], g_a1[G1], g_b1[G1];
__device__ float   g_s2[AF], g_ss2[AF], g_a2[AF], g_b2[AF];

__device__ __forceinline__ float softplus_fast(float x){
    return fmaxf(x, 0.f) + __logf(1.f + __expf(-fabsf(x)));
}

// ---------------- packed f32x2 helpers -----------------------------------
__device__ __forceinline__ u64 pk2(float a, float b){
    u64 r; asm("mov.b64 %0, {%1,%2};" : "=l"(r) : "f"(a), "f"(b)); return r;
}
__device__ __forceinline__ u64 dup2(float a){
    u64 r; asm("mov.b64 %0, {%1,%1};" : "=l"(r) : "f"(a)); return r;
}
__device__ __forceinline__ void fma2(u64 &d, u64 a, u64 b){
    asm("fma.rn.f32x2 %0, %1, %2, %0;" : "+l"(d) : "l"(a), "l"(b));
}
__device__ __forceinline__ float2 up2(u64 v){
    float2 f; asm("mov.b64 {%0,%1}, %2;" : "=f"(f.x), "=f"(f.y) : "l"(v)); return f;
}

// ---------------- embed: x = atom_fea @ W_embed + b ---------------------
__global__ void __launch_bounds__(256) kEmbed(const float* __restrict__ A,
                                              const float* __restrict__ W,
                                              const float* __restrict__ b){
    __shared__ float sW[ORIG*AF];
    __shared__ float sb_[AF];
    __shared__ float sIn[8][4*ORIG];
    int tid = threadIdx.x;
    for (int i = tid; i < ORIG*AF; i += 256) sW[i] = W[i];
    if (tid < AF) sb_[tid] = b[tid];
    __syncthreads();
    int warp = tid >> 5, lane = tid & 31;
    int gw = blockIdx.x*8 + warp, nw = gridDim.x*8;
    float b0 = sb_[lane*2], b1 = sb_[lane*2+1];
    for (int grp = gw; grp < N_ATOMSC/4; grp += nw){
        int base = grp*4;
        for (int i = lane; i < 4*ORIG; i += 32)
            sIn[warp][i] = A[base*ORIG + i];
        __syncwarp();
        float acc[4][2];
        #pragma unroll
        for (int r = 0; r < 4; r++){ acc[r][0] = b0; acc[r][1] = b1; }
        #pragma unroll 4
        for (int k = 0; k < ORIG; k++){
            float2 w = *(const float2*)&sW[k*AF + lane*2];
            #pragma unroll
            for (int r = 0; r < 4; r++){
                float xv = sIn[warp][r*ORIG + k];
                acc[r][0] = fmaf(xv, w.x, acc[r][0]);
                acc[r][1] = fmaf(xv, w.y, acc[r][1]);
            }
        }
        #pragma unroll
        for (int r = 0; r < 4; r++)
            *(float2*)&g_x[(base+r)*AF + lane*2] = make_float2(acc[r][0], acc[r][1]);
        __syncwarp();
    }
}

// ---------------- fused P/Q GEMM (f32x2): 2 atoms per warp ---------------
__global__ void __launch_bounds__(256) kPQ2(const float* __restrict__ Wf){
    extern __shared__ float sW[];          // 64 x 256 floats = 65536 B
    __shared__ float sIn[8][2*AF];
    int tid = threadIdx.x;
    for (int i = tid; i < AF*256; i += 256){
        int k = i >> 8, c = i & 255;
        sW[i] = (c < G1) ? Wf[k*G1 + c] : Wf[(AF + k)*G1 + (c - G1)];
    }
    __syncthreads();
    int warp = tid >> 5, lane = tid & 31;
    int gw = blockIdx.x*8 + warp, nw = gridDim.x*8;
    const float4* sW4 = (const float4*)sW;
    for (int grp = gw; grp < N_ATOMSC/2; grp += nw){
        int base = grp*2;
        for (int i = lane; i < 2*AF; i += 32)
            sIn[warp][i] = g_x[base*AF + i];
        __syncwarp();
        u64 aP[2][2] = {{0,0},{0,0}}, aQ[2][2] = {{0,0},{0,0}};
        #pragma unroll
        for (int c = 0; c < 32; c++){
            float2 e0 = *(const float2*)&sIn[warp][c*2];
            float2 e1 = *(const float2*)&sIn[warp][AF + c*2];
            #pragma unroll
            for (int kk = 0; kk < 2; kk++){
                int k = c*2 + kk;
                float4 wp = sW4[k*64 + lane];
                float4 wq = sW4[k*64 + 32 + lane];
                u64 wp0 = pk2(wp.x, wp.y), wp1 = pk2(wp.z, wp.w);
                u64 wq0 = pk2(wq.x, wq.y), wq1 = pk2(wq.z, wq.w);
                u64 ea = dup2(kk ? e0.y : e0.x);
                u64 eb = dup2(kk ? e1.y : e1.x);
                fma2(aP[0][0], ea, wp0); fma2(aP[0][1], ea, wp1);
                fma2(aQ[0][0], ea, wq0); fma2(aQ[0][1], ea, wq1);
                fma2(aP[1][0], eb, wp0); fma2(aP[1][1], eb, wp1);
                fma2(aQ[1][0], eb, wq0); fma2(aQ[1][1], eb, wq1);
            }
        }
        #pragma unroll
        for (int r = 0; r < 2; r++){
            float2 pl = up2(aP[r][0]), ph = up2(aP[r][1]);
            float2 ql = up2(aQ[r][0]), qh = up2(aQ[r][1]);
            *(float4*)&g_P[(size_t)(base+r)*G1 + lane*4] = make_float4(pl.x, pl.y, ph.x, ph.y);
            *(float4*)&g_Q[(size_t)(base+r)*G1 + lane*4] = make_float4(ql.x, ql.y, qh.x, qh.y);
        }
        __syncwarp();
    }
}

// ---------------- edge kernel (f32x2): 6 rows/warp, fp16 gated out -------
__global__ void __launch_bounds__(256, 3) kEdge(const float* __restrict__ E,
                                                const int*   __restrict__ NI,
                                                const float* __restrict__ Wf,
                                                const float* __restrict__ bf){
    __shared__ float sW[NBRP*G1];          // 21504 B (row 41 zero-padded)
    __shared__ float sb[G1];
    __shared__ float sS[G1], sQ[G1];
    __shared__ float sIn[8][6*NBRP];       // 8064 B
    int tid = threadIdx.x;
    int wid = tid >> 5, lane = tid & 31;
    const float* WfE = Wf + 128*G1;
    for (int i = tid; i < NBRF*G1; i += 256) sW[i] = WfE[i];
    for (int i = NBRF*G1 + tid; i < NBRP*G1; i += 256) sW[i] = 0.f;
    if (tid < G1){ sb[tid] = bf[tid]; sS[tid] = 0.f; sQ[tid] = 0.f; }
    if (lane < 6) sIn[wid][lane*NBRP + 41] = 0.f;   // pad column
    __syncthreads();

    const float4* sW4 = (const float4*)sW;
    float4 bb = *(const float4*)&sb[lane*4];
    float cs0=0,cs1=0,cs2=0,cs3=0, cq0=0,cq1=0,cq2=0,cq3=0;

    int gw = blockIdx.x*8 + wid, nw = gridDim.x*8;
    for (int g = gw; g < NGROUPS; g += nw){
        int n = g >> 1;
        size_t rb = (size_t)g * 6;
        const float* Ew = E + rb * NBRF;
        #pragma unroll
        for (int i = lane; i < 6*NBRF; i += 32){
            int r = i / NBRF, k = i - r*NBRF;
            sIn[wid][r*NBRP + k] = Ew[i];
        }
        float4 p = *(const float4*)&g_P[(size_t)n*G1 + lane*4];
        u64 acc[6][2];
        #pragma unroll
        for (int r = 0; r < 6; r++){
            int j = NI[rb + r];
            float4 q = *(const float4*)&g_Q[(size_t)j*G1 + lane*4];
            acc[r][0] = pk2(bb.x + p.x + q.x, bb.y + p.y + q.y);
            acc[r][1] = pk2(bb.z + p.z + q.z, bb.w + p.w + q.w);
        }
        __syncwarp();
        #pragma unroll
        for (int c = 0; c < 21; c++){
            float2 e[6];
            #pragma unroll
            for (int r = 0; r < 6; r++)
                e[r] = *(const float2*)&sIn[wid][r*NBRP + c*2];
            #pragma unroll
            for (int kk = 0; kk < 2; kk++){
                float4 wv = sW4[(c*2+kk)*32 + lane];
                u64 w0 = pk2(wv.x, wv.y), w1 = pk2(wv.z, wv.w);
                #pragma unroll
                for (int r = 0; r < 6; r++){
                    u64 ee = dup2(kk ? e[r].y : e[r].x);
                    fma2(acc[r][0], ee, w0);
                    fma2(acc[r][1], ee, w1);
                }
            }
        }
        #pragma unroll
        for (int r = 0; r < 6; r++){
            float2 v0 = up2(acc[r][0]), v1 = up2(acc[r][1]);
            __half2 h0 = __float22half2_rn(v0);
            __half2 h1 = __float22half2_rn(v1);
            uint2 st;
            st.x = *(unsigned int*)&h0;
            st.y = *(unsigned int*)&h1;
            *(uint2*)&g_gated[(rb + r)*(G1/2) + lane*2] = st;
            cs0 += v0.x; cq0 = fmaf(v0.x, v0.x, cq0);
            cs1 += v0.y; cq1 = fmaf(v0.y, v0.y, cq1);
            cs2 += v1.x; cq2 = fmaf(v1.x, v1.x, cq2);
            cs3 += v1.y; cq3 = fmaf(v1.y, v1.y, cq3);
        }
        __syncwarp();
    }
    atomicAdd(&sS[lane*4+0], cs0); atomicAdd(&sQ[lane*4+0], cq0);
    atomicAdd(&sS[lane*4+1], cs1); atomicAdd(&sQ[lane*4+1], cq1);
    atomicAdd(&sS[lane*4+2], cs2); atomicAdd(&sQ[lane*4+2], cq2);
    atomicAdd(&sS[lane*4+3], cs3); atomicAdd(&sQ[lane*4+3], cq3);
    __syncthreads();
    if (tid < G1){
        atomicAdd(&g_s1[tid],  sS[tid]);
        atomicAdd(&g_ss1[tid], sQ[tid]);
    }
}

// ---------------- BN1 finalize -------------------------------------------
__global__ void kBN1(const float* __restrict__ gam, const float* __restrict__ bet){
    int f = threadIdx.x;
    float inv = 1.f / (float)NM;
    float m = g_s1[f]*inv;
    float v = g_ss1[f]*inv - m*m;
    float a = gam[f] * rsqrtf(v + EPSL);
    g_a1[f] = a;
    g_b1[f] = bet[f] - m*a;
    g_s1[f] = 0.f; g_ss1[f] = 0.f;
}

// ---------------- reduce: sigmoid*softplus over fp16 gated ----------------
__global__ void __launch_bounds__(256) kReduce(){
    __shared__ float rs[AF], rq[AF];
    int tid = threadIdx.x;
    int wid = tid >> 5, lane = tid & 31;
    if (tid < AF){ rs[tid] = 0.f; rq[tid] = 0.f; }
    __syncthreads();
    int f2 = lane*2;
    float A1x = g_a1[f2],    A1y = g_a1[f2+1];
    float B1x = g_b1[f2],    B1y = g_b1[f2+1];
    float A2x = g_a1[64+f2], A2y = g_a1[64+f2+1];
    float B2x = g_b1[64+f2], B2y = g_b1[64+f2+1];
    float s0=0,s1=0,q0=0,q1=0;
    int gw = blockIdx.x*8 + wid, nw = gridDim.x*8;
    for (int n = gw; n < N_ATOMSC; n += nw){
        const __half2* bh = g_gated + (size_t)n*(M_NBR*(G1/2)) + lane;
        float a0 = 0.f, a1 = 0.f;
        #pragma unroll
        for (int m = 0; m < M_NBR; m++){
            float2 zf = __half22float2(bh[m*64]);
            float2 zc = __half22float2(bh[m*64 + 32]);
            float xf0 = fmaf(zf.x, A1x, B1x);
            float xf1 = fmaf(zf.y, A1y, B1y);
            float xc0 = fmaf(zc.x, A2x, B2x);
            float xc1 = fmaf(zc.y, A2y, B2y);
            float sg0 = __fdividef(1.f, 1.f + __expf(-xf0));
            float sg1 = __fdividef(1.f, 1.f + __expf(-xf1));
            a0 = fmaf(sg0, softplus_fast(xc0), a0);
            a1 = fmaf(sg1, softplus_fast(xc1), a1);
        }
        *(float2*)&g_ns[(size_t)n*AF + f2] = make_float2(a0, a1);
        s0 += a0; q0 = fmaf(a0, a0, q0);
        s1 += a1; q1 = fmaf(a1, a1, q1);
    }
    atomicAdd(&rs[f2],   s0); atomicAdd(&rq[f2],   q0);
    atomicAdd(&rs[f2+1], s1); atomicAdd(&rq[f2+1], q1);
    __syncthreads();
    if (tid < AF){
        atomicAdd(&g_s2[tid],  rs[tid]);
        atomicAdd(&g_ss2[tid], rq[tid]);
    }
}

// ---------------- BN2 finalize ------------------------------------------
__global__ void kBN2(const float* __restrict__ gam, const float* __restrict__ bet){
    int f = threadIdx.x;
    float inv = 1.f / (float)N_ATOMSC;
    float m = g_s2[f]*inv;
    float v = g_ss2[f]*inv - m*m;
    float a = gam[f] * rsqrtf(v + EPSL);
    g_a2[f] = a;
    g_b2[f] = bet[f] - m*a;
    g_s2[f] = 0.f; g_ss2[f] = 0.f;
}

// ---------------- residual update ----------------------------------------
__global__ void __launch_bounds__(256) kUpdate(){
    int i4 = blockIdx.x*256 + threadIdx.x;
    int f = (i4 & 15) * 4;
    float4 xv = *(const float4*)&g_x[i4*4];
    float4 nv = *(const float4*)&g_ns[i4*4];
    float4 a2 = *(const float4*)&g_a2[f];
    float4 b2 = *(const float4*)&g_b2[f];
    float4 o;
    o.x = softplus_fast(xv.x + fmaf(nv.x, a2.x, b2.x));
    o.y = softplus_fast(xv.y + fmaf(nv.y, a2.y, b2.y));
    o.z = softplus_fast(xv.z + fmaf(nv.z, a2.z, b2.z));
    o.w = softplus_fast(xv.w + fmaf(nv.w, a2.w, b2.w));
    *(float4*)&g_x[i4*4] = o;
}

// ---------------- pool + FC + ReLU ---------------------------------------
__global__ void __launch_bounds__(128) kPool(const int* __restrict__ cidx,
                                             const float* __restrict__ Wp,
                                             const float* __restrict__ bp,
                                             float* __restrict__ out){
    __shared__ float sm[AF];
    int c = blockIdx.x, tid = threadIdx.x;
    if (tid < AF){
        float s = 0.f;
        #pragma unroll 5
        for (int a = 0; a < APC; a++){
            int idx = cidx[c*APC + a];
            s += g_x[idx*AF + tid];
        }
        sm[tid] = s * (1.f/(float)APC);
    }
    __syncthreads();
    float acc = bp[tid];
    #pragma unroll 8
    for (int k = 0; k < AF; k++)
        acc = fmaf(sm[k], Wp[k*OUTD + tid], acc);
    out[c*OUTD + tid] = fmaxf(acc, 0.f);
}

// ---------------- launcher ------------------------------------------------
extern "C" void kernel_launch(void* const* d_in, const int* in_sizes, int n_in,
                              void* d_out, int out_size){
    const float* atom_fea = (const float*)d_in[0];
    const float* nbr_fea  = (const float*)d_in[1];
    const int*   nbr_idx  = (const int*)  d_in[2];
    const int*   cidx     = (const int*)  d_in[3];
    const float* W_embed  = (const float*)d_in[4];
    const float* b_embed  = (const float*)d_in[5];
    const float* W_full   = (const float*)d_in[6];
    const float* b_full   = (const float*)d_in[7];
    const float* g1       = (const float*)d_in[8];
    const float* be1      = (const float*)d_in[9];
    const float* g2       = (const float*)d_in[10];
    const float* be2      = (const float*)d_in[11];
    const float* Wp       = (const float*)d_in[12];
    const float* bp       = (const float*)d_in[13];
    float* out = (float*)d_out;

    static int attr_set = 0;
    if (!attr_set){
        cudaFuncSetAttribute(kPQ2, cudaFuncAttributeMaxDynamicSharedMemorySize, AF*256*4);
        attr_set = 1;
    }

    kEmbed<<<512, 256>>>(atom_fea, W_embed, b_embed);
    for (int l = 0; l < 3; l++){
        const float* Wf = W_full + (size_t)l * 169 * G1;
        kPQ2 <<<592, 256, AF*256*4>>>(Wf);
        kEdge<<<444, 256>>>(nbr_fea, nbr_idx, Wf, b_full + l*G1);
        kBN1 <<<1, 128>>>(g1 + l*G1, be1 + l*G1);
        kReduce<<<1024, 256>>>();
        kBN2 <<<1, 64>>>(g2 + l*AF, be2 + l*AF);
        kUpdate<<<(N_ATOMSC*AF/4)/256, 256>>>();
    }
    kPool<<<NCRY, 128>>>(cidx, Wp, bp, out);
}